// round 16
// baseline (speedup 1.0000x reference)
#include <cuda_runtime.h>
#include <cstdint>
#include <cstddef>

#define D        128
#define B        4096
#define S        10
#define L        2
#define NT       3
#define R_ROWS   32           // rows per block
#define WSTRIDE  132          // 128 + 4 pad: quad-stride 33 -> conflict-free LDS.128
#define RNN_THREADS 256

#define NUM_CELLS 2000
#define NUM_DRUGS 4000
#define NUM_GENES 20000

// -------------------- scratch (no allocation allowed) --------------------
__device__ float g_gene_emb[NUM_GENES * D];     // 10.24 MB
__device__ float g_drug_emb[NUM_DRUGS * D];     // 2.05 MB
__device__ float g_h0[B * D];
__device__ float g_h1[B * D];
__device__ float g_agg[L * NT * B * D];         // 12.6 MB

// ==========================================================================
// Projection GEMM:  C[M,128] = A[M,K] @ W[K,128] + bias
// Block tile 64x128, BK=16, 128 threads, 8x8 micro-tile per thread.
// ==========================================================================
__global__ void proj_kernel(const float* __restrict__ A,
                            const float* __restrict__ W,
                            const float* __restrict__ bias,
                            float* __restrict__ C,
                            int M, int K) {
    __shared__ float As[64][17];
    __shared__ float Bs[16][128];

    const int tid = threadIdx.x;
    const int tm  = tid >> 4;
    const int tn  = tid & 15;
    const int row0 = blockIdx.x * 64;

    float acc[8][8];
#pragma unroll
    for (int i = 0; i < 8; i++)
#pragma unroll
        for (int j = 0; j < 8; j++) acc[i][j] = 0.f;

    for (int k0 = 0; k0 < K; k0 += 16) {
#pragma unroll
        for (int i = 0; i < 8; i++) {
            int e  = i * 128 + tid;
            int m  = e >> 4;
            int kk = e & 15;
            int gr = row0 + m;
            As[m][kk] = (gr < M) ? A[(size_t)gr * K + k0 + kk] : 0.f;
        }
#pragma unroll
        for (int i = 0; i < 16; i++) {
            int e  = i * 128 + tid;
            int kk = e >> 7;
            int n  = e & 127;
            Bs[kk][n] = W[(size_t)(k0 + kk) * D + n];
        }
        __syncthreads();

#pragma unroll
        for (int kk = 0; kk < 16; kk++) {
            float a[8], bb[8];
#pragma unroll
            for (int i = 0; i < 8; i++) a[i] = As[tm * 8 + i][kk];
#pragma unroll
            for (int j = 0; j < 8; j++) bb[j] = Bs[kk][tn * 8 + j];
#pragma unroll
            for (int i = 0; i < 8; i++)
#pragma unroll
                for (int j = 0; j < 8; j++)
                    acc[i][j] = fmaf(a[i], bb[j], acc[i][j]);
        }
        __syncthreads();
    }

#pragma unroll
    for (int i = 0; i < 8; i++) {
        int gr = row0 + tm * 8 + i;
        if (gr < M) {
#pragma unroll
            for (int j = 0; j < 8; j++)
                C[(size_t)gr * D + tn * 8 + j] = acc[i][j] + bias[tn * 8 + j];
        }
    }
}

// ==========================================================================
// Gather initial center embeddings:  h0[b] = drug_emb[center_ids[b]]
// ==========================================================================
__global__ void gather_kernel(const int* __restrict__ ids, float* __restrict__ out) {
    int b = blockIdx.x;
    int d = threadIdx.x;
    out[(size_t)b * D + d] = g_drug_emb[(size_t)ids[b] * D + d];
}

// ==========================================================================
// Fused RNN aggregation for ALL (layer, type) pairs.
// grid = (B/32, NT, L), block = 256 threads.
// Thread (dgrp = tid&63, rowgrp = tid>>6) computes output dims
// {dgrp, dgrp+64} for 8 rows rowgrp*8..rowgrp*8+7.
// Per float4 k-chunk: 4 weight LDS + 16 broadcast x/h LDS -> 128 FFMA.
// Wx@x and Wh@h accumulate into ONE accumulator per (row, dim).
// ==========================================================================
__global__ void rnn_kernel(const float* __restrict__ rnn_Wx,
                           const float* __restrict__ rnn_Wh,
                           const float* __restrict__ rnn_b,
                           const int* __restrict__ cell_neigh,
                           const int* __restrict__ drug_neigh,
                           const int* __restrict__ gene_neigh,
                           const float* __restrict__ cell_tab) {
    const int t    = blockIdx.y;
    const int l    = blockIdx.z;
    const int row0 = blockIdx.x * R_ROWS;
    const int dgrp = threadIdx.x & 63;
    const int d0   = dgrp;
    const int d1   = dgrp + 64;
    const int rowgrp = threadIdx.x >> 6;        // 0..3
    const int rbase  = rowgrp * 8;

    extern __shared__ float sm[];
    float* WxT  = sm;                           // [128][WSTRIDE]
    float* WhT  = WxT + 128 * WSTRIDE;          // [128][WSTRIDE]
    float* x_sh = WhT + 128 * WSTRIDE;          // [R_ROWS][128]
    float* h_sh = x_sh + R_ROWS * 128;          // [R_ROWS][128]
    __shared__ int ids[R_ROWS][S];

    // ---- load + transpose weights (coalesced global reads) ----
    const float* Wx = rnn_Wx + (size_t)(l * NT + t) * D * D;
    const float* Wh = rnn_Wh + (size_t)(l * NT + t) * D * D;
    for (int e = threadIdx.x; e < D * D; e += RNN_THREADS) {
        int k  = e >> 7;
        int dd = e & 127;
        WxT[dd * WSTRIDE + k] = Wx[e];
        WhT[dd * WSTRIDE + k] = Wh[e];
    }

    const float* table;
    const int*   neigh;
    if (t == 0)      { table = cell_tab;   neigh = cell_neigh; }
    else if (t == 1) { table = g_drug_emb; neigh = drug_neigh; }
    else             { table = g_gene_emb; neigh = gene_neigh; }

    for (int e = threadIdx.x; e < R_ROWS * S; e += RNN_THREADS) {
        int r = e / S;
        int s = e % S;
        ids[r][s] = neigh[((size_t)l * B + row0 + r) * S + s];
    }
    // zero h_sh
    for (int e = threadIdx.x; e < R_ROWS * D; e += RNN_THREADS)
        h_sh[e] = 0.f;

    const float b0 = rnn_b[(size_t)(l * NT + t) * D + d0];
    const float b1 = rnn_b[(size_t)(l * NT + t) * D + d1];
    __syncthreads();

    // preload x for step 0 (2 dims x 8 rows)
    float xn0[8], xn1[8];
#pragma unroll
    for (int r = 0; r < 8; r++) {
        size_t base = (size_t)ids[rbase + r][0] * D;
        xn0[r] = table[base + d0];
        xn1[r] = table[base + d1];
    }

    float hv0[8], hv1[8];

    const float4* wxp0 = reinterpret_cast<const float4*>(WxT + d0 * WSTRIDE);
    const float4* wxp1 = reinterpret_cast<const float4*>(WxT + d1 * WSTRIDE);
    const float4* whp0 = reinterpret_cast<const float4*>(WhT + d0 * WSTRIDE);
    const float4* whp1 = reinterpret_cast<const float4*>(WhT + d1 * WSTRIDE);

    for (int s = 0; s < S; s++) {
#pragma unroll
        for (int r = 0; r < 8; r++) {
            x_sh[(rbase + r) * D + d0] = xn0[r];
            x_sh[(rbase + r) * D + d1] = xn1[r];
        }
        __syncthreads();

        // prefetch x for next step (hidden under the FMA loop)
        if (s + 1 < S) {
#pragma unroll
            for (int r = 0; r < 8; r++) {
                size_t base = (size_t)ids[rbase + r][s + 1] * D;
                xn0[r] = table[base + d0];
                xn1[r] = table[base + d1];
            }
        }

        float acc0[8], acc1[8];
#pragma unroll
        for (int r = 0; r < 8; r++) { acc0[r] = 0.f; acc1[r] = 0.f; }

#pragma unroll 2
        for (int kq = 0; kq < 32; kq++) {
            float4 wx0 = wxp0[kq];
            float4 wx1 = wxp1[kq];
            float4 wh0 = whp0[kq];
            float4 wh1 = whp1[kq];
#pragma unroll
            for (int r = 0; r < 8; r++) {
                float4 xv = reinterpret_cast<const float4*>(x_sh + (rbase + r) * D)[kq];
                float4 hh = reinterpret_cast<const float4*>(h_sh + (rbase + r) * D)[kq];
                acc0[r] = fmaf(xv.x, wx0.x, acc0[r]);
                acc0[r] = fmaf(xv.y, wx0.y, acc0[r]);
                acc0[r] = fmaf(xv.z, wx0.z, acc0[r]);
                acc0[r] = fmaf(xv.w, wx0.w, acc0[r]);
                acc0[r] = fmaf(hh.x, wh0.x, acc0[r]);
                acc0[r] = fmaf(hh.y, wh0.y, acc0[r]);
                acc0[r] = fmaf(hh.z, wh0.z, acc0[r]);
                acc0[r] = fmaf(hh.w, wh0.w, acc0[r]);
                acc1[r] = fmaf(xv.x, wx1.x, acc1[r]);
                acc1[r] = fmaf(xv.y, wx1.y, acc1[r]);
                acc1[r] = fmaf(xv.z, wx1.z, acc1[r]);
                acc1[r] = fmaf(xv.w, wx1.w, acc1[r]);
                acc1[r] = fmaf(hh.x, wh1.x, acc1[r]);
                acc1[r] = fmaf(hh.y, wh1.y, acc1[r]);
                acc1[r] = fmaf(hh.z, wh1.z, acc1[r]);
                acc1[r] = fmaf(hh.w, wh1.w, acc1[r]);
            }
        }
        __syncthreads();   // all reads of x_sh/h_sh done before overwrite

#pragma unroll
        for (int r = 0; r < 8; r++) {
            hv0[r] = tanhf(b0 + acc0[r]);
            hv1[r] = tanhf(b1 + acc1[r]);
            h_sh[(rbase + r) * D + d0] = hv0[r];
            h_sh[(rbase + r) * D + d1] = hv1[r];
        }
    }

    float* aggp = g_agg + (size_t)(l * NT + t) * B * D;
#pragma unroll
    for (int r = 0; r < 8; r++) {
        aggp[(size_t)(row0 + rbase + r) * D + d0] = hv0[r];
        aggp[(size_t)(row0 + rbase + r) * D + d1] = hv1[r];
    }
}

// ==========================================================================
// Attention combine for one layer.
// ==========================================================================
__global__ void att_kernel(const float* __restrict__ h_in,
                           const float* __restrict__ agg_l,   // [NT][B][D]
                           const float* __restrict__ w,       // [256]
                           float* __restrict__ h_out) {
    const int lane = threadIdx.x & 31;
    const int warp = threadIdx.x >> 5;
    const int b = blockIdx.x * (blockDim.x >> 5) + warp;
    if (b >= B) return;

    float cv[4][4];
#pragma unroll
    for (int j = 0; j < 4; j++)
        cv[0][j] = h_in[(size_t)b * D + lane + 32 * j];
#pragma unroll
    for (int c = 1; c < 4; c++)
#pragma unroll
        for (int j = 0; j < 4; j++)
            cv[c][j] = agg_l[((size_t)(c - 1) * B + b) * D + lane + 32 * j];

    float sself = 0.f;
    float sc[4] = {0.f, 0.f, 0.f, 0.f};
#pragma unroll
    for (int j = 0; j < 4; j++) {
        float w1 = w[lane + 32 * j];
        float w2 = w[128 + lane + 32 * j];
        sself = fmaf(cv[0][j], w1, sself);
#pragma unroll
        for (int c = 0; c < 4; c++)
            sc[c] = fmaf(cv[c][j], w2, sc[c]);
    }
#pragma unroll
    for (int off = 16; off; off >>= 1) {
        sself += __shfl_xor_sync(0xffffffffu, sself, off);
#pragma unroll
        for (int c = 0; c < 4; c++)
            sc[c] += __shfl_xor_sync(0xffffffffu, sc[c], off);
    }

    float scores[4];
#pragma unroll
    for (int c = 0; c < 4; c++) {
        float v = sself + sc[c];
        scores[c] = (v > 0.f) ? v : 0.01f * v;
    }
    float mx = fmaxf(fmaxf(scores[0], scores[1]), fmaxf(scores[2], scores[3]));
    float al[4], esum = 0.f;
#pragma unroll
    for (int c = 0; c < 4; c++) { al[c] = expf(scores[c] - mx); esum += al[c]; }
    float inv = 1.f / esum;
#pragma unroll
    for (int c = 0; c < 4; c++) al[c] *= inv;

#pragma unroll
    for (int j = 0; j < 4; j++) {
        float o = 0.f;
#pragma unroll
        for (int c = 0; c < 4; c++) o = fmaf(al[c], cv[c][j], o);
        h_out[(size_t)b * D + lane + 32 * j] = o;
    }
}

// ==========================================================================
// Launch
// ==========================================================================
extern "C" void kernel_launch(void* const* d_in, const int* in_sizes, int n_in,
                              void* d_out, int out_size) {
    const float* drug_feats = (const float*)d_in[0];
    const float* gene_feats = (const float*)d_in[1];
    const float* cell_tab   = (const float*)d_in[2];
    const float* W_drug     = (const float*)d_in[3];
    const float* b_drug     = (const float*)d_in[4];
    const float* W_gene     = (const float*)d_in[5];
    const float* b_gene     = (const float*)d_in[6];
    const float* rnn_Wx     = (const float*)d_in[7];
    const float* rnn_Wh     = (const float*)d_in[8];
    const float* rnn_b      = (const float*)d_in[9];
    const float* att_w      = (const float*)d_in[10];
    const int*   center_ids = (const int*)d_in[11];
    const int*   cell_neigh = (const int*)d_in[12];
    const int*   drug_neigh = (const int*)d_in[13];
    const int*   gene_neigh = (const int*)d_in[14];
    float* out = (float*)d_out;

    float *p_gene_emb, *p_drug_emb, *p_h0, *p_h1, *p_agg;
    cudaGetSymbolAddress((void**)&p_gene_emb, g_gene_emb);
    cudaGetSymbolAddress((void**)&p_drug_emb, g_drug_emb);
    cudaGetSymbolAddress((void**)&p_h0, g_h0);
    cudaGetSymbolAddress((void**)&p_h1, g_h1);
    cudaGetSymbolAddress((void**)&p_agg, g_agg);

    const int rnn_smem = (2 * 128 * WSTRIDE + 2 * R_ROWS * 128) * (int)sizeof(float); // 167936 B
    cudaFuncSetAttribute((const void*)rnn_kernel,
                         cudaFuncAttributeMaxDynamicSharedMemorySize, rnn_smem);

    // 1) project full tables once (exactly equivalent to projecting gathered rows)
    proj_kernel<<<(NUM_GENES + 63) / 64, 128>>>(gene_feats, W_gene, b_gene,
                                                p_gene_emb, NUM_GENES, 2048);
    proj_kernel<<<(NUM_DRUGS + 63) / 64, 128>>>(drug_feats, W_drug, b_drug,
                                                p_drug_emb, NUM_DRUGS, 1024);

    // 2) initial center embeddings
    gather_kernel<<<B, D>>>(center_ids, p_h0);

    // 3) all 6 (layer, type) RNN aggregations in one launch (independent of h)
    rnn_kernel<<<dim3(B / R_ROWS, NT, L), RNN_THREADS, rnn_smem>>>(
        rnn_Wx, rnn_Wh, rnn_b, cell_neigh, drug_neigh, gene_neigh, cell_tab);

    // 4) attention combines (sequential across layers)
    att_kernel<<<B / 8, 256>>>(p_h0, p_agg, att_w, p_h1);
    att_kernel<<<B / 8, 256>>>(p_h1, p_agg + (size_t)NT * B * D, att_w + 2 * D, out);
}

// round 17
// speedup vs baseline: 1.4617x; 1.4617x over previous
#include <cuda_runtime.h>
#include <cstdint>
#include <cstddef>

#define D        128
#define B        4096
#define S        10
#define L        2
#define NT       3
#define R_ROWS   32           // rows per block (rnn)
#define WSTRIDE  132          // 128 + 4 pad: quad-stride 33 -> conflict-free LDS.128
#define RNN_THREADS 256

#define NUM_CELLS 2000
#define NUM_DRUGS 4000
#define NUM_GENES 20000

// proj tf32 gemm tile config
#define PBM 64
#define PBK 32
#define ASTR 36               // A smem row stride (floats): 36 mod 32 = 4 -> conflict-free frags
#define BSTR 136              // B smem row stride (floats): 136 mod 32 = 8 -> conflict-free frags
#define PROJ_SMEM ((2 * PBM * ASTR + 2 * PBK * BSTR) * 4)   // 53248 B

// -------------------- scratch (no allocation allowed) --------------------
__device__ float g_gene_emb[NUM_GENES * D];     // 10.24 MB
__device__ float g_drug_emb[NUM_DRUGS * D];     // 2.05 MB
__device__ float g_h0[B * D];
__device__ float g_h1[B * D];
__device__ float g_agg[L * NT * B * D];         // 12.6 MB

// ==========================================================================
// helpers for tf32 mma path
// ==========================================================================
__device__ __forceinline__ uint32_t f2tf32(float f) {
    uint32_t u;
    asm("cvt.rna.tf32.f32 %0, %1;" : "=r"(u) : "f"(f));
    return u;
}

__device__ __forceinline__ void mma_tf32(float c[4], const uint32_t a[4], const uint32_t b[2]) {
    asm volatile(
        "mma.sync.aligned.m16n8k8.row.col.f32.tf32.tf32.f32 "
        "{%0,%1,%2,%3}, {%4,%5,%6,%7}, {%8,%9}, {%0,%1,%2,%3};"
        : "+f"(c[0]), "+f"(c[1]), "+f"(c[2]), "+f"(c[3])
        : "r"(a[0]), "r"(a[1]), "r"(a[2]), "r"(a[3]), "r"(b[0]), "r"(b[1]));
}

__device__ __forceinline__ void cp_async16(uint32_t smem_addr, const void* gptr, uint32_t src_bytes) {
    asm volatile("cp.async.cg.shared.global [%0], [%1], 16, %2;"
                 :: "r"(smem_addr), "l"(gptr), "r"(src_bytes));
}
__device__ __forceinline__ void cp_async_commit() {
    asm volatile("cp.async.commit_group;");
}
template <int N>
__device__ __forceinline__ void cp_async_wait() {
    asm volatile("cp.async.wait_group %0;" :: "n"(N));
}

// ==========================================================================
// Projection GEMM (tf32 tensor cores):  C[M,128] = A[M,K] @ W[K,128] + bias
// Block: 256 threads (8 warps, 2x4 warp grid), tile 64x128, BK=32,
// 2-stage cp.async double buffering. Each warp: 32x32, m16n8k8 mma.
// ==========================================================================
__global__ void proj_tf32_kernel(const float* __restrict__ A,
                                 const float* __restrict__ W,
                                 const float* __restrict__ bias,
                                 float* __restrict__ C,
                                 int M, int K) {
    extern __shared__ float sm[];
    float* As = sm;                         // [2][PBM][ASTR]
    float* Bs = sm + 2 * PBM * ASTR;        // [2][PBK][BSTR]

    const int tid   = threadIdx.x;
    const int lane  = tid & 31;
    const int warp  = tid >> 5;
    const int warpM = warp & 1;             // 0..1
    const int warpN = warp >> 1;            // 0..3
    const int gid   = lane >> 2;            // group id 0..7
    const int tig   = lane & 3;             // thread-in-group 0..3
    const int row0  = blockIdx.x * PBM;

    const int nchunks = K / PBK;

    float acc[2][4][4];
#pragma unroll
    for (int mt = 0; mt < 2; mt++)
#pragma unroll
        for (int nt = 0; nt < 4; nt++)
#pragma unroll
            for (int i = 0; i < 4; i++) acc[mt][nt][i] = 0.f;

    // ---- async tile loader ----
    auto issue_chunk = [&](int buf, int chunk) {
        const int k0 = chunk * PBK;
        float* Ab = As + buf * PBM * ASTR;
        float* Bb = Bs + buf * PBK * BSTR;
        // A tile: 64 rows x 32 cols = 512 float4; 2 per thread
#pragma unroll
        for (int i = 0; i < 2; i++) {
            int pos = i * 256 + tid;
            int r   = pos >> 3;             // 0..63
            int c4  = pos & 7;              // 0..7
            int gr  = row0 + r;
            const void* src = A + (size_t)gr * K + k0 + c4 * 4;
            uint32_t dst = (uint32_t)__cvta_generic_to_shared(Ab + r * ASTR + c4 * 4);
            cp_async16(dst, src, (gr < M) ? 16u : 0u);
        }
        // B tile: 32 rows x 128 cols = 1024 float4; 4 per thread (always in-bounds)
#pragma unroll
        for (int i = 0; i < 4; i++) {
            int pos = i * 256 + tid;
            int kr  = pos >> 5;             // 0..31
            int c4  = pos & 31;             // 0..31
            const void* src = W + (size_t)(k0 + kr) * D + c4 * 4;
            uint32_t dst = (uint32_t)__cvta_generic_to_shared(Bb + kr * BSTR + c4 * 4);
            cp_async16(dst, src, 16u);
        }
        cp_async_commit();
    };

    issue_chunk(0, 0);

    for (int c = 0; c < nchunks; c++) {
        const int buf = c & 1;
        if (c + 1 < nchunks) {
            issue_chunk(buf ^ 1, c + 1);
            cp_async_wait<1>();
        } else {
            cp_async_wait<0>();
        }
        __syncthreads();

        const float* Ab = As + buf * PBM * ASTR;
        const float* Bb = Bs + buf * PBK * BSTR;

#pragma unroll
        for (int kk8 = 0; kk8 < 4; kk8++) {
            const int kk = kk8 * 8;
            uint32_t afr[2][4];
#pragma unroll
            for (int mt = 0; mt < 2; mt++) {
                int r = warpM * 32 + mt * 16 + gid;
                afr[mt][0] = f2tf32(Ab[(r)     * ASTR + kk + tig]);
                afr[mt][1] = f2tf32(Ab[(r + 8) * ASTR + kk + tig]);
                afr[mt][2] = f2tf32(Ab[(r)     * ASTR + kk + 4 + tig]);
                afr[mt][3] = f2tf32(Ab[(r + 8) * ASTR + kk + 4 + tig]);
            }
            uint32_t bfr[4][2];
#pragma unroll
            for (int nt = 0; nt < 4; nt++) {
                int ncol = warpN * 32 + nt * 8 + gid;
                bfr[nt][0] = f2tf32(Bb[(kk + tig)     * BSTR + ncol]);
                bfr[nt][1] = f2tf32(Bb[(kk + 4 + tig) * BSTR + ncol]);
            }
#pragma unroll
            for (int mt = 0; mt < 2; mt++)
#pragma unroll
                for (int nt = 0; nt < 4; nt++)
                    mma_tf32(acc[mt][nt], afr[mt], bfr[nt]);
        }
        __syncthreads();   // protect buffer before next issue overwrites it
    }

    // ---- epilogue: add bias, store ----
#pragma unroll
    for (int mt = 0; mt < 2; mt++) {
#pragma unroll
        for (int nt = 0; nt < 4; nt++) {
            int gc = warpN * 32 + nt * 8 + tig * 2;
            float b0v = bias[gc];
            float b1v = bias[gc + 1];
            int gr0 = row0 + warpM * 32 + mt * 16 + gid;
            int gr1 = gr0 + 8;
            if (gr0 < M) {
                float2 v = make_float2(acc[mt][nt][0] + b0v, acc[mt][nt][1] + b1v);
                *reinterpret_cast<float2*>(C + (size_t)gr0 * D + gc) = v;
            }
            if (gr1 < M) {
                float2 v = make_float2(acc[mt][nt][2] + b0v, acc[mt][nt][3] + b1v);
                *reinterpret_cast<float2*>(C + (size_t)gr1 * D + gc) = v;
            }
        }
    }
}

// ==========================================================================
// Gather initial center embeddings:  h0[b] = drug_emb[center_ids[b]]
// ==========================================================================
__global__ void gather_kernel(const int* __restrict__ ids, float* __restrict__ out) {
    int b = blockIdx.x;
    int d = threadIdx.x;
    out[(size_t)b * D + d] = g_drug_emb[(size_t)ids[b] * D + d];
}

// ==========================================================================
// Fused RNN aggregation for ALL (layer, type) pairs. (unchanged from R16)
// ==========================================================================
__global__ void rnn_kernel(const float* __restrict__ rnn_Wx,
                           const float* __restrict__ rnn_Wh,
                           const float* __restrict__ rnn_b,
                           const int* __restrict__ cell_neigh,
                           const int* __restrict__ drug_neigh,
                           const int* __restrict__ gene_neigh,
                           const float* __restrict__ cell_tab) {
    const int t    = blockIdx.y;
    const int l    = blockIdx.z;
    const int row0 = blockIdx.x * R_ROWS;
    const int dgrp = threadIdx.x & 63;
    const int d0   = dgrp;
    const int d1   = dgrp + 64;
    const int rowgrp = threadIdx.x >> 6;        // 0..3
    const int rbase  = rowgrp * 8;

    extern __shared__ float sm[];
    float* WxT  = sm;                           // [128][WSTRIDE]
    float* WhT  = WxT + 128 * WSTRIDE;          // [128][WSTRIDE]
    float* x_sh = WhT + 128 * WSTRIDE;          // [R_ROWS][128]
    float* h_sh = x_sh + R_ROWS * 128;          // [R_ROWS][128]
    __shared__ int ids[R_ROWS][S];

    const float* Wx = rnn_Wx + (size_t)(l * NT + t) * D * D;
    const float* Wh = rnn_Wh + (size_t)(l * NT + t) * D * D;
    for (int e = threadIdx.x; e < D * D; e += RNN_THREADS) {
        int k  = e >> 7;
        int dd = e & 127;
        WxT[dd * WSTRIDE + k] = Wx[e];
        WhT[dd * WSTRIDE + k] = Wh[e];
    }

    const float* table;
    const int*   neigh;
    if (t == 0)      { table = cell_tab;   neigh = cell_neigh; }
    else if (t == 1) { table = g_drug_emb; neigh = drug_neigh; }
    else             { table = g_gene_emb; neigh = gene_neigh; }

    for (int e = threadIdx.x; e < R_ROWS * S; e += RNN_THREADS) {
        int r = e / S;
        int s = e % S;
        ids[r][s] = neigh[((size_t)l * B + row0 + r) * S + s];
    }
    for (int e = threadIdx.x; e < R_ROWS * D; e += RNN_THREADS)
        h_sh[e] = 0.f;

    const float b0 = rnn_b[(size_t)(l * NT + t) * D + d0];
    const float b1 = rnn_b[(size_t)(l * NT + t) * D + d1];
    __syncthreads();

    float xn0[8], xn1[8];
#pragma unroll
    for (int r = 0; r < 8; r++) {
        size_t base = (size_t)ids[rbase + r][0] * D;
        xn0[r] = table[base + d0];
        xn1[r] = table[base + d1];
    }

    float hv0[8], hv1[8];

    const float4* wxp0 = reinterpret_cast<const float4*>(WxT + d0 * WSTRIDE);
    const float4* wxp1 = reinterpret_cast<const float4*>(WxT + d1 * WSTRIDE);
    const float4* whp0 = reinterpret_cast<const float4*>(WhT + d0 * WSTRIDE);
    const float4* whp1 = reinterpret_cast<const float4*>(WhT + d1 * WSTRIDE);

    for (int s = 0; s < S; s++) {
#pragma unroll
        for (int r = 0; r < 8; r++) {
            x_sh[(rbase + r) * D + d0] = xn0[r];
            x_sh[(rbase + r) * D + d1] = xn1[r];
        }
        __syncthreads();

        if (s + 1 < S) {
#pragma unroll
            for (int r = 0; r < 8; r++) {
                size_t base = (size_t)ids[rbase + r][s + 1] * D;
                xn0[r] = table[base + d0];
                xn1[r] = table[base + d1];
            }
        }

        float acc0[8], acc1[8];
#pragma unroll
        for (int r = 0; r < 8; r++) { acc0[r] = 0.f; acc1[r] = 0.f; }

#pragma unroll 2
        for (int kq = 0; kq < 32; kq++) {
            float4 wx0 = wxp0[kq];
            float4 wx1 = wxp1[kq];
            float4 wh0 = whp0[kq];
            float4 wh1 = whp1[kq];
#pragma unroll
            for (int r = 0; r < 8; r++) {
                float4 xv = reinterpret_cast<const float4*>(x_sh + (rbase + r) * D)[kq];
                float4 hh = reinterpret_cast<const float4*>(h_sh + (rbase + r) * D)[kq];
                acc0[r] = fmaf(xv.x, wx0.x, acc0[r]);
                acc0[r] = fmaf(xv.y, wx0.y, acc0[r]);
                acc0[r] = fmaf(xv.z, wx0.z, acc0[r]);
                acc0[r] = fmaf(xv.w, wx0.w, acc0[r]);
                acc0[r] = fmaf(hh.x, wh0.x, acc0[r]);
                acc0[r] = fmaf(hh.y, wh0.y, acc0[r]);
                acc0[r] = fmaf(hh.z, wh0.z, acc0[r]);
                acc0[r] = fmaf(hh.w, wh0.w, acc0[r]);
                acc1[r] = fmaf(xv.x, wx1.x, acc1[r]);
                acc1[r] = fmaf(xv.y, wx1.y, acc1[r]);
                acc1[r] = fmaf(xv.z, wx1.z, acc1[r]);
                acc1[r] = fmaf(xv.w, wx1.w, acc1[r]);
                acc1[r] = fmaf(hh.x, wh1.x, acc1[r]);
                acc1[r] = fmaf(hh.y, wh1.y, acc1[r]);
                acc1[r] = fmaf(hh.z, wh1.z, acc1[r]);
                acc1[r] = fmaf(hh.w, wh1.w, acc1[r]);
            }
        }
        __syncthreads();

#pragma unroll
        for (int r = 0; r < 8; r++) {
            hv0[r] = tanhf(b0 + acc0[r]);
            hv1[r] = tanhf(b1 + acc1[r]);
            h_sh[(rbase + r) * D + d0] = hv0[r];
            h_sh[(rbase + r) * D + d1] = hv1[r];
        }
    }

    float* aggp = g_agg + (size_t)(l * NT + t) * B * D;
#pragma unroll
    for (int r = 0; r < 8; r++) {
        aggp[(size_t)(row0 + rbase + r) * D + d0] = hv0[r];
        aggp[(size_t)(row0 + rbase + r) * D + d1] = hv1[r];
    }
}

// ==========================================================================
// Attention combine for one layer.
// ==========================================================================
__global__ void att_kernel(const float* __restrict__ h_in,
                           const float* __restrict__ agg_l,   // [NT][B][D]
                           const float* __restrict__ w,       // [256]
                           float* __restrict__ h_out) {
    const int lane = threadIdx.x & 31;
    const int warp = threadIdx.x >> 5;
    const int b = blockIdx.x * (blockDim.x >> 5) + warp;
    if (b >= B) return;

    float cv[4][4];
#pragma unroll
    for (int j = 0; j < 4; j++)
        cv[0][j] = h_in[(size_t)b * D + lane + 32 * j];
#pragma unroll
    for (int c = 1; c < 4; c++)
#pragma unroll
        for (int j = 0; j < 4; j++)
            cv[c][j] = agg_l[((size_t)(c - 1) * B + b) * D + lane + 32 * j];

    float sself = 0.f;
    float sc[4] = {0.f, 0.f, 0.f, 0.f};
#pragma unroll
    for (int j = 0; j < 4; j++) {
        float w1 = w[lane + 32 * j];
        float w2 = w[128 + lane + 32 * j];
        sself = fmaf(cv[0][j], w1, sself);
#pragma unroll
        for (int c = 0; c < 4; c++)
            sc[c] = fmaf(cv[c][j], w2, sc[c]);
    }
#pragma unroll
    for (int off = 16; off; off >>= 1) {
        sself += __shfl_xor_sync(0xffffffffu, sself, off);
#pragma unroll
        for (int c = 0; c < 4; c++)
            sc[c] += __shfl_xor_sync(0xffffffffu, sc[c], off);
    }

    float scores[4];
#pragma unroll
    for (int c = 0; c < 4; c++) {
        float v = sself + sc[c];
        scores[c] = (v > 0.f) ? v : 0.01f * v;
    }
    float mx = fmaxf(fmaxf(scores[0], scores[1]), fmaxf(scores[2], scores[3]));
    float al[4], esum = 0.f;
#pragma unroll
    for (int c = 0; c < 4; c++) { al[c] = expf(scores[c] - mx); esum += al[c]; }
    float inv = 1.f / esum;
#pragma unroll
    for (int c = 0; c < 4; c++) al[c] *= inv;

#pragma unroll
    for (int j = 0; j < 4; j++) {
        float o = 0.f;
#pragma unroll
        for (int c = 0; c < 4; c++) o = fmaf(al[c], cv[c][j], o);
        h_out[(size_t)b * D + lane + 32 * j] = o;
    }
}

// ==========================================================================
// Launch
// ==========================================================================
extern "C" void kernel_launch(void* const* d_in, const int* in_sizes, int n_in,
                              void* d_out, int out_size) {
    const float* drug_feats = (const float*)d_in[0];
    const float* gene_feats = (const float*)d_in[1];
    const float* cell_tab   = (const float*)d_in[2];
    const float* W_drug     = (const float*)d_in[3];
    const float* b_drug     = (const float*)d_in[4];
    const float* W_gene     = (const float*)d_in[5];
    const float* b_gene     = (const float*)d_in[6];
    const float* rnn_Wx     = (const float*)d_in[7];
    const float* rnn_Wh     = (const float*)d_in[8];
    const float* rnn_b      = (const float*)d_in[9];
    const float* att_w      = (const float*)d_in[10];
    const int*   center_ids = (const int*)d_in[11];
    const int*   cell_neigh = (const int*)d_in[12];
    const int*   drug_neigh = (const int*)d_in[13];
    const int*   gene_neigh = (const int*)d_in[14];
    float* out = (float*)d_out;

    float *p_gene_emb, *p_drug_emb, *p_h0, *p_h1, *p_agg;
    cudaGetSymbolAddress((void**)&p_gene_emb, g_gene_emb);
    cudaGetSymbolAddress((void**)&p_drug_emb, g_drug_emb);
    cudaGetSymbolAddress((void**)&p_h0, g_h0);
    cudaGetSymbolAddress((void**)&p_h1, g_h1);
    cudaGetSymbolAddress((void**)&p_agg, g_agg);

    const int rnn_smem = (2 * 128 * WSTRIDE + 2 * R_ROWS * 128) * (int)sizeof(float); // 167936 B
    cudaFuncSetAttribute((const void*)rnn_kernel,
                         cudaFuncAttributeMaxDynamicSharedMemorySize, rnn_smem);
    cudaFuncSetAttribute((const void*)proj_tf32_kernel,
                         cudaFuncAttributeMaxDynamicSharedMemorySize, PROJ_SMEM);

    // 1) project full tables once (tf32 tensor cores)
    proj_tf32_kernel<<<(NUM_GENES + PBM - 1) / PBM, 256, PROJ_SMEM>>>(
        gene_feats, W_gene, b_gene, p_gene_emb, NUM_GENES, 2048);
    proj_tf32_kernel<<<(NUM_DRUGS + PBM - 1) / PBM, 256, PROJ_SMEM>>>(
        drug_feats, W_drug, b_drug, p_drug_emb, NUM_DRUGS, 1024);

    // 2) initial center embeddings
    gather_kernel<<<B, D>>>(center_ids, p_h0);

    // 3) all 6 (layer, type) RNN aggregations in one launch
    rnn_kernel<<<dim3(B / R_ROWS, NT, L), RNN_THREADS, rnn_smem>>>(
        rnn_Wx, rnn_Wh, rnn_b, cell_neigh, drug_neigh, gene_neigh, cell_tab);

    // 4) attention combines (sequential across layers)
    att_kernel<<<B / 8, 256>>>(p_h0, p_agg, att_w, p_h1);
    att_kernel<<<B / 8, 256>>>(p_h1, p_agg + (size_t)NT * B * D, att_w + 2 * D, out);
}